// round 15
// baseline (speedup 1.0000x reference)
#include <cuda_runtime.h>
#include <cuda_fp16.h>

// ===========================================================================
// B=128, N=512, H=512.  Output: [probs 65536 | new_last_hh 65536] fp32
// fp16 mma.sync + ldmatrix big GEMM (legacy-HMMA-rate bound), fused epilogues.
// R14 + fat setup kernel + gru/denc fuse + softmax/context fuse + 4-stage ring.
// ===========================================================================

// -------------------- scratch (byte offsets) --------------------------------
#define OFF_SH     0L                       // stat fp16 [65536][512]
#define OFF_BH     67108864L                // Bcat fp16 [1536][512]
#define OFF_FL     68681728L                // float region
#define SCRATCH_BYTES (OFF_FL + 4718592L)
__device__ __align__(1024) unsigned char g_scratch[SCRATCH_BYTES];

// float sub-offsets (in floats) inside FL region
#define FO_GX     0L
#define FO_GH     196608L
#define FO_HNEW   393216L
#define FO_DENC   458752L
#define FO_DTGT   524288L
#define FO_SSTATE 589824L
#define FO_CPTR   655360L
#define FO_CTPTR  720896L
#define FO_CTXE   786432L
#define FO_CTXT   851968L
#define FO_SCE    917504L
#define FO_SCT    983040L

// ===================== PTX helpers (baseline ISA only) ======================
__device__ __forceinline__ unsigned smem_u32(const void* p) {
    unsigned a;
    asm("{ .reg .u64 t; cvta.to.shared.u64 t, %1; cvt.u32.u64 %0, t; }"
        : "=r"(a) : "l"(p));
    return a;
}
__device__ __forceinline__ void cp16(unsigned dst, const void* src) {
    asm volatile("cp.async.cg.shared.global [%0], [%1], 16;" :: "r"(dst), "l"(src));
}
#define CP_COMMIT() asm volatile("cp.async.commit_group;" ::: "memory")
#define CP_WAIT2()  asm volatile("cp.async.wait_group 2;" ::: "memory")
#define CP_WAIT1()  asm volatile("cp.async.wait_group 1;" ::: "memory")
#define CP_WAIT0()  asm volatile("cp.async.wait_group 0;" ::: "memory")

__device__ __forceinline__ void mma16816(float c[4],
        unsigned a0, unsigned a1, unsigned a2, unsigned a3,
        unsigned b0, unsigned b1) {
    asm volatile(
        "mma.sync.aligned.m16n8k16.row.col.f32.f16.f16.f32 "
        "{%0,%1,%2,%3}, {%4,%5,%6,%7}, {%8,%9}, {%0,%1,%2,%3};"
        : "+f"(c[0]), "+f"(c[1]), "+f"(c[2]), "+f"(c[3])
        : "r"(a0), "r"(a1), "r"(a2), "r"(a3), "r"(b0), "r"(b1));
}
__device__ __forceinline__ void ldsm4(unsigned r[4], unsigned addr) {
    asm volatile("ldmatrix.sync.aligned.m8n8.x4.shared.b16 {%0,%1,%2,%3}, [%4];"
        : "=r"(r[0]), "=r"(r[1]), "=r"(r[2]), "=r"(r[3]) : "r"(addr));
}

// tanh(x) = 1 - 2/(e^{2x}+1) with MUFU ex2/rcp (rel err ~1e-7).
__device__ __forceinline__ float fast_tanh(float x) {
    float e, r;
    asm("ex2.approx.f32 %0, %1;" : "=f"(e) : "f"(x * 2.8853900817779268f));
    asm("rcp.approx.f32 %0, %1;" : "=f"(r) : "f"(e + 1.0f));
    return 1.0f - 2.0f * r;
}

// ===========================================================================
// Small-GEMM body (proven R14): C tile 32x64 = A[128x512] @ W^T slice.
// K-chunk 64 with register prefetch; scalar SMEM stores (stride-65 rows).
// ===========================================================================
__device__ __forceinline__ void sg_body(
    const float* __restrict__ A, const float* __restrict__ W,
    int ldw, int wofs, float* __restrict__ C, int ldc,
    int row0, int col0, int t, float (*As)[65], float (*Ws)[65])
{
    int c = t & 63, rg = t >> 6;
    int arow = t >> 3, ak = (t & 7) * 8;
    int wrow = t >> 2, wk = (t & 3) * 16;
    const float* Ap = A + (size_t)(row0 + arow) * 512 + ak;
    const float* Wp = W + (size_t)(col0 + wrow) * ldw + wofs + wk;

    float acc[8];
#pragma unroll
    for (int i = 0; i < 8; i++) acc[i] = 0.f;

    float4 a0 = *(const float4*)(Ap);
    float4 a1 = *(const float4*)(Ap + 4);
    float4 w0 = *(const float4*)(Wp);
    float4 w1 = *(const float4*)(Wp + 4);
    float4 w2 = *(const float4*)(Wp + 8);
    float4 w3 = *(const float4*)(Wp + 12);

    for (int k0 = 0; k0 < 512; k0 += 64) {
        As[arow][ak]     = a0.x; As[arow][ak + 1] = a0.y;
        As[arow][ak + 2] = a0.z; As[arow][ak + 3] = a0.w;
        As[arow][ak + 4] = a1.x; As[arow][ak + 5] = a1.y;
        As[arow][ak + 6] = a1.z; As[arow][ak + 7] = a1.w;
        Ws[wrow][wk]      = w0.x; Ws[wrow][wk + 1]  = w0.y;
        Ws[wrow][wk + 2]  = w0.z; Ws[wrow][wk + 3]  = w0.w;
        Ws[wrow][wk + 4]  = w1.x; Ws[wrow][wk + 5]  = w1.y;
        Ws[wrow][wk + 6]  = w1.z; Ws[wrow][wk + 7]  = w1.w;
        Ws[wrow][wk + 8]  = w2.x; Ws[wrow][wk + 9]  = w2.y;
        Ws[wrow][wk + 10] = w2.z; Ws[wrow][wk + 11] = w2.w;
        Ws[wrow][wk + 12] = w3.x; Ws[wrow][wk + 13] = w3.y;
        Ws[wrow][wk + 14] = w3.z; Ws[wrow][wk + 15] = w3.w;
        __syncthreads();
        if (k0 + 64 < 512) {
            a0 = *(const float4*)(Ap + k0 + 64);
            a1 = *(const float4*)(Ap + k0 + 68);
            w0 = *(const float4*)(Wp + k0 + 64);
            w1 = *(const float4*)(Wp + k0 + 68);
            w2 = *(const float4*)(Wp + k0 + 72);
            w3 = *(const float4*)(Wp + k0 + 76);
        }
#pragma unroll
        for (int kk = 0; kk < 64; kk++) {
            float wv = Ws[c][kk];
#pragma unroll
            for (int i = 0; i < 8; i++)
                acc[i] += As[rg * 8 + i][kk] * wv;
        }
        __syncthreads();
    }
#pragma unroll
    for (int i = 0; i < 8; i++)
        C[(size_t)(row0 + rg * 8 + i) * ldc + col0 + c] = acc[i];
}

// ===========================================================================
// Fat setup kernel: all input-independent work in one launch.
//   blocks [0,96)    : gx  = dech @ wih^T      (24 x 4 tiles)
//   blocks [96,192)  : gh  = lhh  @ whh^T      (24 x 4 tiles)
//   blocks [192,224) : dtgt   = tgth @ tgtW_d^T (8 x 4)
//   blocks [224,256) : sstate = semb @ ptrW_e^T (8 x 4)
//   blocks [256,1024): convert Bcat -> fp16
//   blocks [1024,...): convert stat -> fp16
// ===========================================================================
__global__ void __launch_bounds__(256)
setup_fat_k(const float* __restrict__ dech, const float* __restrict__ lhh,
            const float* __restrict__ tgth, const float* __restrict__ semb,
            const float* __restrict__ wih, const float* __restrict__ whh,
            const float* __restrict__ encW, const float* __restrict__ tgtW,
            const float* __restrict__ ptrW, const float* __restrict__ stat,
            float* __restrict__ gx, float* __restrict__ gh,
            float* __restrict__ dtgt, float* __restrict__ sstate,
            __half2* __restrict__ bh2, __half2* __restrict__ sh2)
{
    __shared__ float As[32][65];
    __shared__ float Ws[64][65];
    int bid = blockIdx.x, t = threadIdx.x;
    if (bid < 96) {
        sg_body(dech, wih, 512, 0, gx, 1536, (bid / 24) * 32, (bid % 24) * 64, t, As, Ws);
    } else if (bid < 192) {
        int lb = bid - 96;
        sg_body(lhh, whh, 512, 0, gh, 1536, (lb / 24) * 32, (lb % 24) * 64, t, As, Ws);
    } else if (bid < 224) {
        int lb = bid - 192;
        sg_body(tgth, tgtW, 1024, 512, dtgt, 512, (lb / 8) * 32, (lb % 8) * 64, t, As, Ws);
    } else if (bid < 256) {
        int lb = bid - 224;
        sg_body(semb, ptrW, 1536, 1024, sstate, 512, (lb / 8) * 32, (lb % 8) * 64, t, As, Ws);
    } else if (bid < 1024) {
        int i = (bid - 256) * 256 + t;               // 196608 quads
        int e = i * 4;
        int row = e >> 9, k = e & 511;
        const float* src;
        if (row < 512)       src = encW + (size_t)row * 1024 + k;
        else if (row < 1024) src = tgtW + (size_t)(row - 512) * 1024 + k;
        else                 src = ptrW + (size_t)(row - 1024) * 1536 + k;
        float4 v = *(const float4*)src;
        bh2[2 * i]     = __floats2half2_rn(v.x, v.y);
        bh2[2 * i + 1] = __floats2half2_rn(v.z, v.w);
    } else {
        size_t i = (size_t)(bid - 1024) * 256 + t;   // 8388608 quads
        float4 v = ((const float4*)stat)[i];
        sh2[2 * i]     = __floats2half2_rn(v.x, v.y);
        sh2[2 * i + 1] = __floats2half2_rn(v.z, v.w);
    }
}

// ===========================================================================
// GRU gates fused with denc GEMM.  grid (8,4): each block computes h_new for
// its 32 rows (redundant across x; identical values), writes hnew + out, then
// computes its denc tile = hnew @ enc_Wd^T.
// ===========================================================================
__global__ void __launch_bounds__(256)
gru_denc_k(const float* __restrict__ gx, const float* __restrict__ gh,
           const float* __restrict__ bih, const float* __restrict__ bhh,
           const float* __restrict__ lhh, const float* __restrict__ encW,
           float* __restrict__ outh, float* __restrict__ hnewg,
           float* __restrict__ denc)
{
    __shared__ float As[32][65];
    __shared__ float Ws[64][65];
    int t = threadIdx.x;
    int row0 = blockIdx.y * 32, col0 = blockIdx.x * 64;

    for (int i = t; i < 32 * 512; i += 256) {
        int r = i >> 9, j = i & 511;
        int b = row0 + r;
        const float* gxb = gx + b * 1536;
        const float* ghb = gh + b * 1536;
        float xr = gxb[j] + bih[j],              hr = ghb[j] + bhh[j];
        float xz = gxb[512 + j] + bih[512 + j],  hz = ghb[512 + j] + bhh[512 + j];
        float xn = gxb[1024 + j] + bih[1024 + j];
        float hn = ghb[1024 + j] + bhh[1024 + j];
        float rr = 1.f / (1.f + expf(-(xr + hr)));
        float zz = 1.f / (1.f + expf(-(xz + hz)));
        float nn = tanhf(xn + rr * hn);
        float h = lhh[b * 512 + j];
        float v = (1.f - zz) * nn + zz * h;
        hnewg[b * 512 + j] = v;
        if (blockIdx.x == 0) outh[b * 512 + j] = v;
    }
    __syncthreads();   // block-local visibility of hnewg writes (this block wrote all rows it reads)
    sg_body(hnewg, encW, 1024, 512, denc, 512, row0, col0, t, As, Ws);
}

// ===========================================================================
// Small GEMM, z-batched (standalone, for cptr/ctptr projections)
// ===========================================================================
__global__ void __launch_bounds__(256)
small_gemm3_k(const float* A0, const float* W0, int ldw0, int wofs0, float* C0, int ldc0,
              const float* A1, const float* W1, int ldw1, int wofs1, float* C1, int ldc1,
              const float* A2, const float* W2, int ldw2, int wofs2, float* C2, int ldc2)
{
    __shared__ float As[32][65];
    __shared__ float Ws[64][65];
    int z = blockIdx.z;
    const float* A = (z == 0) ? A0 : (z == 1) ? A1 : A2;
    const float* W = (z == 0) ? W0 : (z == 1) ? W1 : W2;
    int ldw  = (z == 0) ? ldw0  : (z == 1) ? ldw1  : ldw2;
    int wofs = (z == 0) ? wofs0 : (z == 1) ? wofs1 : wofs2;
    float* C = (z == 0) ? C0 : (z == 1) ? C1 : C2;
    int ldc  = (z == 0) ? ldc0 : (z == 1) ? ldc1 : ldc2;
    sg_body(A, W, ldw, wofs, C, ldc, blockIdx.y * 32, blockIdx.x * 64,
            threadIdx.x, As, Ws);
}

// ===========================================================================
// Big-GEMM shared mainloop constants: 4-stage cp.async ring, ONE sync per kt.
// SMEM: [0,81920) 4 stages x (A tile 10240 + B tile 10240)
// ===========================================================================
#define TILE_B   10240
#define STAGE_B  20480
#define RING_B   81920
// et extras
#define SM_DV    81920
#define SM_VV    83968
#define SM_RED   86016
#define SMEM_ET  88064
// ptr extras
#define SM_A1    81920
#define SM_A2    83968
#define SM_PV    86016
#define SM_RED2  88064
#define SMEM_PTR 92160

__device__ __forceinline__ void load_stage(
    unsigned sbase, unsigned bufbase, int kt, int t, int row0, int grow,
    const __half* __restrict__ sh, const __half* __restrict__ bh)
{
    int tsel = t >> 7;           // 0:A 1:B
    int tt = t & 127;
    const __half* base = tsel ? bh : sh;
    int roff = tsel ? grow : row0;
    unsigned stile = sbase + bufbase + (unsigned)(tsel * TILE_B) + (unsigned)(tt * 80);
    const __half* src = base + (size_t)(roff + tt) * 512 + kt * 32;
#pragma unroll
    for (int c = 0; c < 4; c++)
        cp16(stile + (unsigned)(c * 16), src + c * 8);
}

// ===========================================================================
// enc/tgt GEMM + score epilogue.  grid (2, 512)
// ===========================================================================
__global__ void __launch_bounds__(256, 2)
big_mma_et_k(const __half* __restrict__ sh, const __half* __restrict__ bh,
             const float* __restrict__ denc, const float* __restrict__ dtgt,
             const float* __restrict__ encv, const float* __restrict__ tgtv,
             float* __restrict__ sc_e, float* __restrict__ sc_t)
{
    extern __shared__ __align__(128) unsigned char smem[];
    unsigned sbase = smem_u32(smem);
    int t = threadIdx.x;
    int lane = t & 31, wid = t >> 5;
    int wm = wid & 1, wn = wid >> 1;
    int qr = lane >> 2, qc = lane & 3;
    int g = blockIdx.x;
    int row0 = blockIdx.y * 128;
    int b = blockIdx.y >> 2;
    int grow = g * 512;

    int lrow = lane & 7, lsel = lane >> 3;
    unsigned a_off = (unsigned)((wm * 64 + (lsel & 1) * 8 + lrow) * 80 + (lsel >> 1) * 16);
    unsigned b_off = (unsigned)((wn * 32 + (lsel >> 1) * 8 + lrow) * 80 + (lsel & 1) * 16);

    float* DV  = (float*)(smem + SM_DV);
    float* VV  = (float*)(smem + SM_VV);
    float* RED = (float*)(smem + SM_RED);
    {
        const float* dsrc = g ? dtgt : denc;
        const float* vsrc = g ? tgtv : encv;
        for (int i = t; i < 512; i += 256) { DV[i] = dsrc[b * 512 + i]; VV[i] = vsrc[i]; }
    }

    float sacc[4][2];
#pragma unroll
    for (int i = 0; i < 4; i++) { sacc[i][0] = 0.f; sacc[i][1] = 0.f; }

    for (int ht = 0; ht < 4; ht++) {
        int gr = grow + ht * 128;
        float acc[4][4][4];
#pragma unroll
        for (int mi = 0; mi < 4; mi++)
#pragma unroll
            for (int nj = 0; nj < 4; nj++)
#pragma unroll
                for (int r = 0; r < 4; r++) acc[mi][nj][r] = 0.f;

        load_stage(sbase, 0, 0, t, row0, gr, sh, bh);
        CP_COMMIT();
        load_stage(sbase, STAGE_B, 1, t, row0, gr, sh, bh);
        CP_COMMIT();

        for (int kt = 0; kt < 16; kt++) {
            unsigned buf = (unsigned)((kt & 3) * STAGE_B);
            if (kt + 2 < 16) {
                load_stage(sbase, (unsigned)(((kt + 2) & 3) * STAGE_B), kt + 2,
                           t, row0, gr, sh, bh);
                CP_COMMIT();
                CP_WAIT2();
            } else if (kt + 1 < 16) {
                CP_WAIT1();
            } else {
                CP_WAIT0();
            }
            __syncthreads();                 // single barrier per iteration (4-stage ring)

            unsigned A = sbase + buf;
            unsigned B = A + TILE_B;
#pragma unroll
            for (int k16 = 0; k16 < 2; k16++) {
                unsigned kb = (unsigned)(k16 * 32);
                unsigned a[4][4], bb[2][4];
#pragma unroll
                for (int mi = 0; mi < 4; mi++)
                    ldsm4(a[mi], A + a_off + mi * 1280 + kb);
#pragma unroll
                for (int np = 0; np < 2; np++)
                    ldsm4(bb[np], B + b_off + np * 1280 + kb);
#pragma unroll
                for (int mi = 0; mi < 4; mi++)
#pragma unroll
                    for (int nj = 0; nj < 4; nj++)
                        mma16816(acc[mi][nj], a[mi][0], a[mi][1], a[mi][2], a[mi][3],
                                 bb[nj >> 1][(nj & 1) * 2], bb[nj >> 1][(nj & 1) * 2 + 1]);
            }
        }

#pragma unroll
        for (int mi = 0; mi < 4; mi++)
#pragma unroll
            for (int nj = 0; nj < 4; nj++) {
                int c0 = ht * 128 + wn * 32 + nj * 8 + qc * 2;
                float d0 = DV[c0], d1 = DV[c0 + 1];
                float v0 = VV[c0], v1 = VV[c0 + 1];
                sacc[mi][0] += v0 * fast_tanh(acc[mi][nj][0] + d0)
                             + v1 * fast_tanh(acc[mi][nj][1] + d1);
                sacc[mi][1] += v0 * fast_tanh(acc[mi][nj][2] + d0)
                             + v1 * fast_tanh(acc[mi][nj][3] + d1);
            }
    }

#pragma unroll
    for (int mi = 0; mi < 4; mi++) {
#pragma unroll
        for (int h = 0; h < 2; h++) {
            float s = sacc[mi][h];
            s += __shfl_xor_sync(0xffffffffu, s, 1);
            s += __shfl_xor_sync(0xffffffffu, s, 2);
            sacc[mi][h] = s;
        }
    }
    __syncthreads();                         // all warps done with mainloop slots
    if (qc == 0) {
#pragma unroll
        for (int mi = 0; mi < 4; mi++) {
            int r = wm * 64 + mi * 16 + qr;
            RED[wn * 128 + r]     = sacc[mi][0];
            RED[wn * 128 + r + 8] = sacc[mi][1];
        }
    }
    __syncthreads();
    if (t < 128) {
        float s = RED[t] + RED[128 + t] + RED[256 + t] + RED[384 + t];
        (g ? sc_t : sc_e)[row0 + t] = s;
    }
}

// ===========================================================================
// ptr GEMM with fused final pointer-score epilogue.  grid (512).
// ===========================================================================
__global__ void __launch_bounds__(256, 2)
big_mma_ptr_k(const __half* __restrict__ sh, const __half* __restrict__ bh,
              const float* __restrict__ cptr, const float* __restrict__ ctptr,
              const float* __restrict__ ss, const float* __restrict__ vp,
              float* __restrict__ out)
{
    extern __shared__ __align__(128) unsigned char smem[];
    unsigned sbase = smem_u32(smem);
    int t = threadIdx.x;
    int lane = t & 31, wid = t >> 5;
    int wm = wid & 1, wn = wid >> 1;
    int qr = lane >> 2, qc = lane & 3;
    int row0 = blockIdx.x * 128;
    int b = blockIdx.x >> 2;

    int lrow = lane & 7, lsel = lane >> 3;
    unsigned a_off = (unsigned)((wm * 64 + (lsel & 1) * 8 + lrow) * 80 + (lsel >> 1) * 16);
    unsigned b_off = (unsigned)((wn * 32 + (lsel >> 1) * 8 + lrow) * 80 + (lsel & 1) * 16);

    float* A1  = (float*)(smem + SM_A1);
    float* A2  = (float*)(smem + SM_A2);
    float* PV  = (float*)(smem + SM_PV);
    float* RED = (float*)(smem + SM_RED2);
    for (int i = t; i < 512; i += 256) {
        float s0 = ss[b * 512 + i];
        A1[i] = cptr[b * 512 + i] + s0;
        A2[i] = ctptr[b * 512 + i] + s0;
        PV[i] = vp[i];
    }

    float s1a[4][2], s2a[4][2];
#pragma unroll
    for (int i = 0; i < 4; i++) {
        s1a[i][0] = 0.f; s1a[i][1] = 0.f;
        s2a[i][0] = 0.f; s2a[i][1] = 0.f;
    }

    for (int ht = 0; ht < 4; ht++) {
        int gr = 1024 + ht * 128;
        float acc[4][4][4];
#pragma unroll
        for (int mi = 0; mi < 4; mi++)
#pragma unroll
            for (int nj = 0; nj < 4; nj++)
#pragma unroll
                for (int r = 0; r < 4; r++) acc[mi][nj][r] = 0.f;

        load_stage(sbase, 0, 0, t, row0, gr, sh, bh);
        CP_COMMIT();
        load_stage(sbase, STAGE_B, 1, t, row0, gr, sh, bh);
        CP_COMMIT();

        for (int kt = 0; kt < 16; kt++) {
            unsigned buf = (unsigned)((kt & 3) * STAGE_B);
            if (kt + 2 < 16) {
                load_stage(sbase, (unsigned)(((kt + 2) & 3) * STAGE_B), kt + 2,
                           t, row0, gr, sh, bh);
                CP_COMMIT();
                CP_WAIT2();
            } else if (kt + 1 < 16) {
                CP_WAIT1();
            } else {
                CP_WAIT0();
            }
            __syncthreads();                 // single barrier per iteration

            unsigned A = sbase + buf;
            unsigned B = A + TILE_B;
#pragma unroll
            for (int k16 = 0; k16 < 2; k16++) {
                unsigned kb = (unsigned)(k16 * 32);
                unsigned a[4][4], bb[2][4];
#pragma unroll
                for (int mi = 0; mi < 4; mi++)
                    ldsm4(a[mi], A + a_off + mi * 1280 + kb);
#pragma unroll
                for (int np = 0; np < 2; np++)
                    ldsm4(bb[np], B + b_off + np * 1280 + kb);
#pragma unroll
                for (int mi = 0; mi < 4; mi++)
#pragma unroll
                    for (int nj = 0; nj < 4; nj++)
                        mma16816(acc[mi][nj], a[mi][0], a[mi][1], a[mi][2], a[mi][3],
                                 bb[nj >> 1][(nj & 1) * 2], bb[nj >> 1][(nj & 1) * 2 + 1]);
            }
        }

        // fused pointer-score epilogue for this ht block
#pragma unroll
        for (int mi = 0; mi < 4; mi++)
#pragma unroll
            for (int nj = 0; nj < 4; nj++) {
                int c0 = ht * 128 + wn * 32 + nj * 8 + qc * 2;
                float a10 = A1[c0], a11 = A1[c0 + 1];
                float a20 = A2[c0], a21 = A2[c0 + 1];
                float v0 = PV[c0], v1 = PV[c0 + 1];
                float x0 = acc[mi][nj][0], x1 = acc[mi][nj][1];
                float x2 = acc[mi][nj][2], x3 = acc[mi][nj][3];
                s1a[mi][0] += v0 * fast_tanh(x0 + a10) + v1 * fast_tanh(x1 + a11);
                s2a[mi][0] += v0 * fast_tanh(x0 + a20) + v1 * fast_tanh(x1 + a21);
                s1a[mi][1] += v0 * fast_tanh(x2 + a10) + v1 * fast_tanh(x3 + a11);
                s2a[mi][1] += v0 * fast_tanh(x2 + a20) + v1 * fast_tanh(x3 + a21);
            }
    }

#pragma unroll
    for (int mi = 0; mi < 4; mi++) {
#pragma unroll
        for (int h = 0; h < 2; h++) {
            float s1 = s1a[mi][h], s2 = s2a[mi][h];
            s1 += __shfl_xor_sync(0xffffffffu, s1, 1);
            s1 += __shfl_xor_sync(0xffffffffu, s1, 2);
            s2 += __shfl_xor_sync(0xffffffffu, s2, 1);
            s2 += __shfl_xor_sync(0xffffffffu, s2, 2);
            s1a[mi][h] = s1; s2a[mi][h] = s2;
        }
    }
    __syncthreads();
    if (qc == 0) {
#pragma unroll
        for (int mi = 0; mi < 4; mi++) {
            int r = wm * 64 + mi * 16 + qr;
            RED[wn * 256 + r * 2]            = s1a[mi][0];
            RED[wn * 256 + r * 2 + 1]        = s2a[mi][0];
            RED[wn * 256 + (r + 8) * 2]      = s1a[mi][1];
            RED[wn * 256 + (r + 8) * 2 + 1]  = s2a[mi][1];
        }
    }
    __syncthreads();
    if (t < 128) {
        float s1 = RED[t * 2]     + RED[256 + t * 2]     + RED[512 + t * 2]     + RED[768 + t * 2];
        float s2 = RED[t * 2 + 1] + RED[256 + t * 2 + 1] + RED[512 + t * 2 + 1] + RED[768 + t * 2 + 1];
        out[row0 + t] = 5.0f * s1 + s2;
    }
}

// ===========================================================================
// Fused softmax + context: each block recomputes the per-batch softmax
// locally (deterministic), then reduces its half of the context.
// grid 256 (b = bid>>1, half = bid&1), 128 threads.
// ===========================================================================
__global__ void __launch_bounds__(128)
ctx_softmax_k(const __half2* __restrict__ sh2,
              const float* __restrict__ sc_e, const float* __restrict__ sc_t,
              float* __restrict__ ce, float* __restrict__ ct)
{
    int b = blockIdx.x >> 1;
    int half = blockIdx.x & 1;
    int t = threadIdx.x;
    __shared__ float sae[512], sat[512], red[128];

    float ve[4], vt[4];
#pragma unroll
    for (int k = 0; k < 4; k++) {
        ve[k] = sc_e[b * 512 + t + k * 128];
        vt[k] = sc_t[b * 512 + t + k * 128];
    }
    // max reductions
    red[t] = fmaxf(fmaxf(ve[0], ve[1]), fmaxf(ve[2], ve[3]));
    __syncthreads();
    for (int s = 64; s > 0; s >>= 1) {
        if (t < s) red[t] = fmaxf(red[t], red[t + s]);
        __syncthreads();
    }
    float mxe = red[0];
    __syncthreads();
    red[t] = fmaxf(fmaxf(vt[0], vt[1]), fmaxf(vt[2], vt[3]));
    __syncthreads();
    for (int s = 64; s > 0; s >>= 1) {
        if (t < s) red[t] = fmaxf(red[t], red[t + s]);
        __syncthreads();
    }
    float mxt = red[0];
    __syncthreads();
    float ee[4], et_[4];
#pragma unroll
    for (int k = 0; k < 4; k++) { ee[k] = expf(ve[k] - mxe); et_[k] = expf(vt[k] - mxt); }
    red[t] = ee[0] + ee[1] + ee[2] + ee[3];
    __syncthreads();
    for (int s = 64; s > 0; s >>= 1) {
        if (t < s) red[t] += red[t + s];
        __syncthreads();
    }
    float inve = 1.f / red[0];
    __syncthreads();
    red[t] = et_[0] + et_[1] + et_[2] + et_[3];
    __syncthreads();
    for (int s = 64; s > 0; s >>= 1) {
        if (t < s) red[t] += red[t + s];
        __syncthreads();
    }
    float invt = 1.f / red[0];
    __syncthreads();
#pragma unroll
    for (int k = 0; k < 4; k++) {
        sae[t + k * 128] = ee[k] * inve;
        sat[t + k * 128] = et_[k] * invt;
    }
    __syncthreads();

    int h2 = half * 128 + t;                 // 0..255 half2-index
    const __half2* Sb = sh2 + (size_t)b * 131072 + h2;
    float se0 = 0.f, se1 = 0.f, st0 = 0.f, st1 = 0.f;
#pragma unroll 16
    for (int n = 0; n < 512; n++) {
        float2 f = __half22float2(Sb[(size_t)n * 256]);
        float a = sae[n], tt = sat[n];
        se0 += a * f.x;  se1 += a * f.y;
        st0 += tt * f.x; st1 += tt * f.y;
    }
    ce[b * 512 + h2 * 2]     = se0;
    ce[b * 512 + h2 * 2 + 1] = se1;
    ct[b * 512 + h2 * 2]     = st0;
    ct[b * 512 + h2 * 2 + 1] = st1;
}

// ===========================================================================
extern "C" void kernel_launch(void* const* d_in, const int* in_sizes, int n_in,
                              void* d_out, int out_size)
{
    const float* stat = (const float*)d_in[0];   // (128,512,512)
    const float* semb = (const float*)d_in[1];   // (128,1,512)
    const float* dech = (const float*)d_in[2];   // (128,1,512)
    const float* tgth = (const float*)d_in[3];   // (128,1,512)
    const float* lhh  = (const float*)d_in[4];   // (1,128,512)
    const float* ptrv = (const float*)d_in[5];   // (1,1,512)
    const float* ptrW = (const float*)d_in[6];   // (1,512,1536)
    const float* encv = (const float*)d_in[7];   // (1,1,512)
    const float* encW = (const float*)d_in[8];   // (1,512,1024)
    const float* tgtv = (const float*)d_in[9];   // (1,1,512)
    const float* tgtW = (const float*)d_in[10];  // (1,512,1024)
    const float* wih  = (const float*)d_in[11];  // (1536,512)
    const float* whh  = (const float*)d_in[12];  // (1536,512)
    const float* bih  = (const float*)d_in[13];
    const float* bhh  = (const float*)d_in[14];
    float* out = (float*)d_out;

    unsigned char* base = nullptr;
    cudaGetSymbolAddress((void**)&base, g_scratch);
    __half* sh = (__half*)(base + OFF_SH);
    __half* bhp = (__half*)(base + OFF_BH);
    float* FL = (float*)(base + OFF_FL);
    float* gx     = FL + FO_GX;
    float* gh     = FL + FO_GH;
    float* hnew   = FL + FO_HNEW;
    float* denc   = FL + FO_DENC;
    float* dtgt   = FL + FO_DTGT;
    float* sstate = FL + FO_SSTATE;
    float* cptr   = FL + FO_CPTR;
    float* ctptr  = FL + FO_CTPTR;
    float* ctxe   = FL + FO_CTXE;
    float* ctxt   = FL + FO_CTXT;
    float* sc_e   = FL + FO_SCE;
    float* sc_t   = FL + FO_SCT;

    // Attribute cache: set once on the (uncaptured) correctness call.
    static bool attr_done = false;
    if (!attr_done) {
        cudaFuncSetAttribute(big_mma_et_k, cudaFuncAttributeMaxDynamicSharedMemorySize,
                             SMEM_ET);
        cudaFuncSetAttribute(big_mma_ptr_k, cudaFuncAttributeMaxDynamicSharedMemorySize,
                             SMEM_PTR);
        attr_done = true;
    }

    // 1) all independent setup work in one launch
    setup_fat_k<<<33792, 256>>>(dech, lhh, tgth, semb, wih, whh, encW, tgtW, ptrW,
                                stat, gx, gh, dtgt, sstate,
                                (__half2*)bhp, (__half2*)sh);

    // 2) GRU gates fused with denc projection (also writes new_last_hh)
    gru_denc_k<<<dim3(8, 4), 256>>>(gx, gh, bih, bhh, lhh, encW,
                                    out + 65536, hnew, denc);

    // 3) enc/tgt GEMM -> scores
    big_mma_et_k<<<dim3(2, 512), 256, SMEM_ET>>>(sh, bhp, denc, dtgt,
                                                 encv, tgtv, sc_e, sc_t);

    // 4) fused softmax + contexts
    ctx_softmax_k<<<256, 128>>>((const __half2*)sh, sc_e, sc_t, ctxe, ctxt);

    // 5) context projections
    small_gemm3_k<<<dim3(8, 4, 2), 256>>>(
        ctxe, ptrW, 1536, 512, cptr,  512,
        ctxt, ptrW, 1536, 512, ctptr, 512,
        ctxt, ptrW, 1536, 512, ctptr, 512);

    // 6) ptr GEMM with fused final pointer-score epilogue -> probs
    big_mma_ptr_k<<<512, 256, SMEM_PTR>>>(sh, bhp, cptr, ctptr, sstate, ptrv, out);
}

// round 16
// speedup vs baseline: 1.7691x; 1.7691x over previous
#include <cuda_runtime.h>
#include <cuda_fp16.h>

// ===========================================================================
// B=128, N=512, H=512.  Output: [probs 65536 | new_last_hh 65536] fp32
// fp16 mma.sync + ldmatrix big GEMM (legacy-HMMA-rate bound), fused epilogues.
// R14 baseline + fused softmax/context (2x parallel) + merged conversions.
// ===========================================================================

// -------------------- scratch (byte offsets) --------------------------------
#define OFF_SH     0L                       // stat fp16 [65536][512]
#define OFF_BH     67108864L                // Bcat fp16 [1536][512]
#define OFF_FL     68681728L                // float region
#define SCRATCH_BYTES (OFF_FL + 4718592L)
__device__ __align__(1024) unsigned char g_scratch[SCRATCH_BYTES];

// float sub-offsets (in floats) inside FL region
#define FO_GX     0L
#define FO_GH     196608L
#define FO_HNEW   393216L
#define FO_DENC   458752L
#define FO_DTGT   524288L
#define FO_SSTATE 589824L
#define FO_CPTR   655360L
#define FO_CTPTR  720896L
#define FO_CTXE   786432L
#define FO_CTXT   851968L
#define FO_SCE    917504L
#define FO_SCT    983040L

// ===================== PTX helpers (baseline ISA only) ======================
__device__ __forceinline__ unsigned smem_u32(const void* p) {
    unsigned a;
    asm("{ .reg .u64 t; cvta.to.shared.u64 t, %1; cvt.u32.u64 %0, t; }"
        : "=r"(a) : "l"(p));
    return a;
}
__device__ __forceinline__ void cp16(unsigned dst, const void* src) {
    asm volatile("cp.async.cg.shared.global [%0], [%1], 16;" :: "r"(dst), "l"(src));
}
#define CP_COMMIT() asm volatile("cp.async.commit_group;" ::: "memory")
#define CP_WAIT2()  asm volatile("cp.async.wait_group 2;" ::: "memory")
#define CP_WAIT1()  asm volatile("cp.async.wait_group 1;" ::: "memory")
#define CP_WAIT0()  asm volatile("cp.async.wait_group 0;" ::: "memory")

__device__ __forceinline__ void mma16816(float c[4],
        unsigned a0, unsigned a1, unsigned a2, unsigned a3,
        unsigned b0, unsigned b1) {
    asm volatile(
        "mma.sync.aligned.m16n8k16.row.col.f32.f16.f16.f32 "
        "{%0,%1,%2,%3}, {%4,%5,%6,%7}, {%8,%9}, {%0,%1,%2,%3};"
        : "+f"(c[0]), "+f"(c[1]), "+f"(c[2]), "+f"(c[3])
        : "r"(a0), "r"(a1), "r"(a2), "r"(a3), "r"(b0), "r"(b1));
}
__device__ __forceinline__ void ldsm4(unsigned r[4], unsigned addr) {
    asm volatile("ldmatrix.sync.aligned.m8n8.x4.shared.b16 {%0,%1,%2,%3}, [%4];"
        : "=r"(r[0]), "=r"(r[1]), "=r"(r[2]), "=r"(r[3]) : "r"(addr));
}

// tanh(x) = 1 - 2/(e^{2x}+1) with MUFU ex2/rcp (rel err ~1e-7).
__device__ __forceinline__ float fast_tanh(float x) {
    float e, r;
    asm("ex2.approx.f32 %0, %1;" : "=f"(e) : "f"(x * 2.8853900817779268f));
    asm("rcp.approx.f32 %0, %1;" : "=f"(r) : "f"(e + 1.0f));
    return 1.0f - 2.0f * r;
}

// ===========================================================================
// Merged fp32 -> fp16 conversion: blocks [0,768) = Bcat, [768, 33536) = stat.
// Both paths register-light, zero SMEM (no occupancy coupling).
// ===========================================================================
__global__ void __launch_bounds__(256)
convert_all_k(const float* __restrict__ encW, const float* __restrict__ tgtW,
              const float* __restrict__ ptrW, const float* __restrict__ stat,
              __half2* __restrict__ bh2, __half2* __restrict__ sh2)
{
    int bid = blockIdx.x, t = threadIdx.x;
    if (bid < 768) {
        int i = bid * 256 + t;                       // 196608 quads
        int e = i * 4;
        int row = e >> 9, k = e & 511;
        const float* src;
        if (row < 512)       src = encW + (size_t)row * 1024 + k;
        else if (row < 1024) src = tgtW + (size_t)(row - 512) * 1024 + k;
        else                 src = ptrW + (size_t)(row - 1024) * 1536 + k;
        float4 v = *(const float4*)src;
        bh2[2 * i]     = __floats2half2_rn(v.x, v.y);
        bh2[2 * i + 1] = __floats2half2_rn(v.z, v.w);
    } else {
        size_t i = (size_t)(bid - 768) * 256 + t;    // 8388608 quads
        float4 v = ((const float4*)stat)[i];
        sh2[2 * i]     = __floats2half2_rn(v.x, v.y);
        sh2[2 * i + 1] = __floats2half2_rn(v.z, v.w);
    }
}

// ===========================================================================
// Small GEMM, z-batched, register-prefetched: C[128 x N] = A[128x512] @ W^T
// tile 32 rows x 64 cols, K-chunk 64 (8 iterations), 256 threads.
// SMEM stores are SCALAR (stride-65 rows are not 16B aligned).
// ===========================================================================
__global__ void __launch_bounds__(256)
small_gemm3_k(const float* A0, const float* W0, int ldw0, int wofs0, float* C0, int ldc0,
              const float* A1, const float* W1, int ldw1, int wofs1, float* C1, int ldc1,
              const float* A2, const float* W2, int ldw2, int wofs2, float* C2, int ldc2)
{
    int z = blockIdx.z;
    const float* A = (z == 0) ? A0 : (z == 1) ? A1 : A2;
    const float* W = (z == 0) ? W0 : (z == 1) ? W1 : W2;
    int ldw  = (z == 0) ? ldw0  : (z == 1) ? ldw1  : ldw2;
    int wofs = (z == 0) ? wofs0 : (z == 1) ? wofs1 : wofs2;
    float* C = (z == 0) ? C0 : (z == 1) ? C1 : C2;
    int ldc  = (z == 0) ? ldc0 : (z == 1) ? ldc1 : ldc2;

    __shared__ float As[32][65];
    __shared__ float Ws[64][65];
    int t = threadIdx.x;
    int c = t & 63, rg = t >> 6;
    int row0 = blockIdx.y * 32, col0 = blockIdx.x * 64;

    int arow = t >> 3, ak = (t & 7) * 8;
    int wrow = t >> 2, wk = (t & 3) * 16;
    const float* Ap = A + (size_t)(row0 + arow) * 512 + ak;
    const float* Wp = W + (size_t)(col0 + wrow) * ldw + wofs + wk;

    float acc[8];
#pragma unroll
    for (int i = 0; i < 8; i++) acc[i] = 0.f;

    float4 a0 = *(const float4*)(Ap);
    float4 a1 = *(const float4*)(Ap + 4);
    float4 w0 = *(const float4*)(Wp);
    float4 w1 = *(const float4*)(Wp + 4);
    float4 w2 = *(const float4*)(Wp + 8);
    float4 w3 = *(const float4*)(Wp + 12);

    for (int k0 = 0; k0 < 512; k0 += 64) {
        As[arow][ak]     = a0.x; As[arow][ak + 1] = a0.y;
        As[arow][ak + 2] = a0.z; As[arow][ak + 3] = a0.w;
        As[arow][ak + 4] = a1.x; As[arow][ak + 5] = a1.y;
        As[arow][ak + 6] = a1.z; As[arow][ak + 7] = a1.w;
        Ws[wrow][wk]      = w0.x; Ws[wrow][wk + 1]  = w0.y;
        Ws[wrow][wk + 2]  = w0.z; Ws[wrow][wk + 3]  = w0.w;
        Ws[wrow][wk + 4]  = w1.x; Ws[wrow][wk + 5]  = w1.y;
        Ws[wrow][wk + 6]  = w1.z; Ws[wrow][wk + 7]  = w1.w;
        Ws[wrow][wk + 8]  = w2.x; Ws[wrow][wk + 9]  = w2.y;
        Ws[wrow][wk + 10] = w2.z; Ws[wrow][wk + 11] = w2.w;
        Ws[wrow][wk + 12] = w3.x; Ws[wrow][wk + 13] = w3.y;
        Ws[wrow][wk + 14] = w3.z; Ws[wrow][wk + 15] = w3.w;
        __syncthreads();
        if (k0 + 64 < 512) {
            a0 = *(const float4*)(Ap + k0 + 64);
            a1 = *(const float4*)(Ap + k0 + 68);
            w0 = *(const float4*)(Wp + k0 + 64);
            w1 = *(const float4*)(Wp + k0 + 68);
            w2 = *(const float4*)(Wp + k0 + 72);
            w3 = *(const float4*)(Wp + k0 + 76);
        }
#pragma unroll
        for (int kk = 0; kk < 64; kk++) {
            float wv = Ws[c][kk];
#pragma unroll
            for (int i = 0; i < 8; i++)
                acc[i] += As[rg * 8 + i][kk] * wv;
        }
        __syncthreads();
    }
#pragma unroll
    for (int i = 0; i < 8; i++)
        C[(size_t)(row0 + rg * 8 + i) * ldc + col0 + c] = acc[i];
}

// ===========================================================================
__global__ void gru_gates_k(const float* __restrict__ gx, const float* __restrict__ gh,
                            const float* __restrict__ bih, const float* __restrict__ bhh,
                            const float* __restrict__ lhh,
                            float* __restrict__ hnew, float* __restrict__ outh)
{
    int i = blockIdx.x * blockDim.x + threadIdx.x;
    int b = i >> 9, j = i & 511;
    const float* gxb = gx + b * 1536;
    const float* ghb = gh + b * 1536;
    float xr = gxb[j] + bih[j],              hr = ghb[j] + bhh[j];
    float xz = gxb[512 + j] + bih[512 + j],  hz = ghb[512 + j] + bhh[512 + j];
    float xn = gxb[1024 + j] + bih[1024 + j];
    float hn = ghb[1024 + j] + bhh[1024 + j];
    float r = 1.f / (1.f + expf(-(xr + hr)));
    float z = 1.f / (1.f + expf(-(xz + hz)));
    float n = tanhf(xn + r * hn);
    float h = lhh[i];
    float v = (1.f - z) * n + z * h;
    hnew[i] = v;
    outh[i] = v;
}

// ===========================================================================
// Big-GEMM shared mainloop constants (R14-proven 3-stage ring).
// SMEM: [0,61440) 3 stages x (A tile + B tile), tile = 128 rows x 80B
// ===========================================================================
#define TILE_B   10240
#define STAGE_B  20480
// et kernel extras
#define SM_DV    61440
#define SM_VV    63488
#define SM_RED   65536
#define SMEM_ET  67584
// ptr kernel extras
#define SM_A1    61440
#define SM_A2    63488
#define SM_PV    65536
#define SM_RED2  67584
#define SMEM_PTR 71680

__device__ __forceinline__ void load_stage(
    unsigned sbase, unsigned bufbase, int kt, int t, int row0, int grow,
    const __half* __restrict__ sh, const __half* __restrict__ bh)
{
    int tsel = t >> 7;           // 0:A 1:B
    int tt = t & 127;
    const __half* base = tsel ? bh : sh;
    int roff = tsel ? grow : row0;
    unsigned stile = sbase + bufbase + (unsigned)(tsel * TILE_B) + (unsigned)(tt * 80);
    const __half* src = base + (size_t)(roff + tt) * 512 + kt * 32;
#pragma unroll
    for (int c = 0; c < 4; c++)
        cp16(stile + (unsigned)(c * 16), src + c * 8);
}

// ===========================================================================
// enc/tgt GEMM + score epilogue.  grid (2, 512): g = {enc, tgt}
// ===========================================================================
__global__ void __launch_bounds__(256, 2)
big_mma_et_k(const __half* __restrict__ sh, const __half* __restrict__ bh,
             const float* __restrict__ denc, const float* __restrict__ dtgt,
             const float* __restrict__ encv, const float* __restrict__ tgtv,
             float* __restrict__ sc_e, float* __restrict__ sc_t)
{
    extern __shared__ __align__(128) unsigned char smem[];
    unsigned sbase = smem_u32(smem);
    int t = threadIdx.x;
    int lane = t & 31, wid = t >> 5;
    int wm = wid & 1, wn = wid >> 1;
    int qr = lane >> 2, qc = lane & 3;
    int g = blockIdx.x;
    int row0 = blockIdx.y * 128;
    int b = blockIdx.y >> 2;
    int grow = g * 512;

    int lrow = lane & 7, lsel = lane >> 3;
    unsigned a_off = (unsigned)((wm * 64 + (lsel & 1) * 8 + lrow) * 80 + (lsel >> 1) * 16);
    unsigned b_off = (unsigned)((wn * 32 + (lsel >> 1) * 8 + lrow) * 80 + (lsel & 1) * 16);

    float* DV  = (float*)(smem + SM_DV);
    float* VV  = (float*)(smem + SM_VV);
    float* RED = (float*)(smem + SM_RED);
    {
        const float* dsrc = g ? dtgt : denc;
        const float* vsrc = g ? tgtv : encv;
        for (int i = t; i < 512; i += 256) { DV[i] = dsrc[b * 512 + i]; VV[i] = vsrc[i]; }
    }

    float sacc[4][2];
#pragma unroll
    for (int i = 0; i < 4; i++) { sacc[i][0] = 0.f; sacc[i][1] = 0.f; }

    for (int ht = 0; ht < 4; ht++) {
        int gr = grow + ht * 128;
        float acc[4][4][4];
#pragma unroll
        for (int mi = 0; mi < 4; mi++)
#pragma unroll
            for (int nj = 0; nj < 4; nj++)
#pragma unroll
                for (int r = 0; r < 4; r++) acc[mi][nj][r] = 0.f;

        load_stage(sbase, 0, 0, t, row0, gr, sh, bh);
        CP_COMMIT();
        load_stage(sbase, STAGE_B, 1, t, row0, gr, sh, bh);
        CP_COMMIT();

        for (int kt = 0; kt < 16; kt++) {
            unsigned buf = (unsigned)((kt % 3) * STAGE_B);
            if (kt + 2 < 16) {
                unsigned nslot = (unsigned)(((kt + 2) % 3) * STAGE_B);
                load_stage(sbase, nslot, kt + 2, t, row0, gr, sh, bh);
                CP_COMMIT();
                CP_WAIT2();
            } else if (kt + 1 < 16) {
                CP_WAIT1();
            } else {
                CP_WAIT0();
            }
            __syncthreads();

            unsigned A = sbase + buf;
            unsigned B = A + TILE_B;
#pragma unroll
            for (int k16 = 0; k16 < 2; k16++) {
                unsigned kb = (unsigned)(k16 * 32);
                unsigned a[4][4], bb[2][4];
#pragma unroll
                for (int mi = 0; mi < 4; mi++)
                    ldsm4(a[mi], A + a_off + mi * 1280 + kb);
#pragma unroll
                for (int np = 0; np < 2; np++)
                    ldsm4(bb[np], B + b_off + np * 1280 + kb);
#pragma unroll
                for (int mi = 0; mi < 4; mi++)
#pragma unroll
                    for (int nj = 0; nj < 4; nj++)
                        mma16816(acc[mi][nj], a[mi][0], a[mi][1], a[mi][2], a[mi][3],
                                 bb[nj >> 1][(nj & 1) * 2], bb[nj >> 1][(nj & 1) * 2 + 1]);
            }
            __syncthreads();
        }

#pragma unroll
        for (int mi = 0; mi < 4; mi++)
#pragma unroll
            for (int nj = 0; nj < 4; nj++) {
                int c0 = ht * 128 + wn * 32 + nj * 8 + qc * 2;
                float d0 = DV[c0], d1 = DV[c0 + 1];
                float v0 = VV[c0], v1 = VV[c0 + 1];
                sacc[mi][0] += v0 * fast_tanh(acc[mi][nj][0] + d0)
                             + v1 * fast_tanh(acc[mi][nj][1] + d1);
                sacc[mi][1] += v0 * fast_tanh(acc[mi][nj][2] + d0)
                             + v1 * fast_tanh(acc[mi][nj][3] + d1);
            }
    }

#pragma unroll
    for (int mi = 0; mi < 4; mi++) {
#pragma unroll
        for (int h = 0; h < 2; h++) {
            float s = sacc[mi][h];
            s += __shfl_xor_sync(0xffffffffu, s, 1);
            s += __shfl_xor_sync(0xffffffffu, s, 2);
            sacc[mi][h] = s;
        }
    }
    if (qc == 0) {
#pragma unroll
        for (int mi = 0; mi < 4; mi++) {
            int r = wm * 64 + mi * 16 + qr;
            RED[wn * 128 + r]     = sacc[mi][0];
            RED[wn * 128 + r + 8] = sacc[mi][1];
        }
    }
    __syncthreads();
    if (t < 128) {
        float s = RED[t] + RED[128 + t] + RED[256 + t] + RED[384 + t];
        (g ? sc_t : sc_e)[row0 + t] = s;
    }
}

// ===========================================================================
// ptr GEMM with fused final pointer-score epilogue.  grid (512).
// ===========================================================================
__global__ void __launch_bounds__(256, 2)
big_mma_ptr_k(const __half* __restrict__ sh, const __half* __restrict__ bh,
              const float* __restrict__ cptr, const float* __restrict__ ctptr,
              const float* __restrict__ ss, const float* __restrict__ vp,
              float* __restrict__ out)
{
    extern __shared__ __align__(128) unsigned char smem[];
    unsigned sbase = smem_u32(smem);
    int t = threadIdx.x;
    int lane = t & 31, wid = t >> 5;
    int wm = wid & 1, wn = wid >> 1;
    int qr = lane >> 2, qc = lane & 3;
    int row0 = blockIdx.x * 128;
    int b = blockIdx.x >> 2;

    int lrow = lane & 7, lsel = lane >> 3;
    unsigned a_off = (unsigned)((wm * 64 + (lsel & 1) * 8 + lrow) * 80 + (lsel >> 1) * 16);
    unsigned b_off = (unsigned)((wn * 32 + (lsel >> 1) * 8 + lrow) * 80 + (lsel & 1) * 16);

    float* A1  = (float*)(smem + SM_A1);
    float* A2  = (float*)(smem + SM_A2);
    float* PV  = (float*)(smem + SM_PV);
    float* RED = (float*)(smem + SM_RED2);
    for (int i = t; i < 512; i += 256) {
        float s0 = ss[b * 512 + i];
        A1[i] = cptr[b * 512 + i] + s0;
        A2[i] = ctptr[b * 512 + i] + s0;
        PV[i] = vp[i];
    }

    float s1a[4][2], s2a[4][2];
#pragma unroll
    for (int i = 0; i < 4; i++) {
        s1a[i][0] = 0.f; s1a[i][1] = 0.f;
        s2a[i][0] = 0.f; s2a[i][1] = 0.f;
    }

    for (int ht = 0; ht < 4; ht++) {
        int gr = 1024 + ht * 128;
        float acc[4][4][4];
#pragma unroll
        for (int mi = 0; mi < 4; mi++)
#pragma unroll
            for (int nj = 0; nj < 4; nj++)
#pragma unroll
                for (int r = 0; r < 4; r++) acc[mi][nj][r] = 0.f;

        load_stage(sbase, 0, 0, t, row0, gr, sh, bh);
        CP_COMMIT();
        load_stage(sbase, STAGE_B, 1, t, row0, gr, sh, bh);
        CP_COMMIT();

        for (int kt = 0; kt < 16; kt++) {
            unsigned buf = (unsigned)((kt % 3) * STAGE_B);
            if (kt + 2 < 16) {
                unsigned nslot = (unsigned)(((kt + 2) % 3) * STAGE_B);
                load_stage(sbase, nslot, kt + 2, t, row0, gr, sh, bh);
                CP_COMMIT();
                CP_WAIT2();
            } else if (kt + 1 < 16) {
                CP_WAIT1();
            } else {
                CP_WAIT0();
            }
            __syncthreads();

            unsigned A = sbase + buf;
            unsigned B = A + TILE_B;
#pragma unroll
            for (int k16 = 0; k16 < 2; k16++) {
                unsigned kb = (unsigned)(k16 * 32);
                unsigned a[4][4], bb[2][4];
#pragma unroll
                for (int mi = 0; mi < 4; mi++)
                    ldsm4(a[mi], A + a_off + mi * 1280 + kb);
#pragma unroll
                for (int np = 0; np < 2; np++)
                    ldsm4(bb[np], B + b_off + np * 1280 + kb);
#pragma unroll
                for (int mi = 0; mi < 4; mi++)
#pragma unroll
                    for (int nj = 0; nj < 4; nj++)
                        mma16816(acc[mi][nj], a[mi][0], a[mi][1], a[mi][2], a[mi][3],
                                 bb[nj >> 1][(nj & 1) * 2], bb[nj >> 1][(nj & 1) * 2 + 1]);
            }
            __syncthreads();
        }

        // fused pointer-score epilogue for this ht block
#pragma unroll
        for (int mi = 0; mi < 4; mi++)
#pragma unroll
            for (int nj = 0; nj < 4; nj++) {
                int c0 = ht * 128 + wn * 32 + nj * 8 + qc * 2;
                float a10 = A1[c0], a11 = A1[c0 + 1];
                float a20 = A2[c0], a21 = A2[c0 + 1];
                float v0 = PV[c0], v1 = PV[c0 + 1];
                float x0 = acc[mi][nj][0], x1 = acc[mi][nj][1];
                float x2 = acc[mi][nj][2], x3 = acc[mi][nj][3];
                s1a[mi][0] += v0 * fast_tanh(x0 + a10) + v1 * fast_tanh(x1 + a11);
                s2a[mi][0] += v0 * fast_tanh(x0 + a20) + v1 * fast_tanh(x1 + a21);
                s1a[mi][1] += v0 * fast_tanh(x2 + a10) + v1 * fast_tanh(x3 + a11);
                s2a[mi][1] += v0 * fast_tanh(x2 + a20) + v1 * fast_tanh(x3 + a21);
            }
    }

#pragma unroll
    for (int mi = 0; mi < 4; mi++) {
#pragma unroll
        for (int h = 0; h < 2; h++) {
            float s1 = s1a[mi][h], s2 = s2a[mi][h];
            s1 += __shfl_xor_sync(0xffffffffu, s1, 1);
            s1 += __shfl_xor_sync(0xffffffffu, s1, 2);
            s2 += __shfl_xor_sync(0xffffffffu, s2, 1);
            s2 += __shfl_xor_sync(0xffffffffu, s2, 2);
            s1a[mi][h] = s1; s2a[mi][h] = s2;
        }
    }
    if (qc == 0) {
#pragma unroll
        for (int mi = 0; mi < 4; mi++) {
            int r = wm * 64 + mi * 16 + qr;
            RED[wn * 256 + r * 2]            = s1a[mi][0];
            RED[wn * 256 + r * 2 + 1]        = s2a[mi][0];
            RED[wn * 256 + (r + 8) * 2]      = s1a[mi][1];
            RED[wn * 256 + (r + 8) * 2 + 1]  = s2a[mi][1];
        }
    }
    __syncthreads();
    if (t < 128) {
        float s1 = RED[t * 2]     + RED[256 + t * 2]     + RED[512 + t * 2]     + RED[768 + t * 2];
        float s2 = RED[t * 2 + 1] + RED[256 + t * 2 + 1] + RED[512 + t * 2 + 1] + RED[768 + t * 2 + 1];
        out[row0 + t] = 5.0f * s1 + s2;
    }
}

// ===========================================================================
// Fused softmax + context, 2x parallelism over n.
// grid 256 (b = bid>>1, half = bid&1), 256 threads:
//   thread t: h2 = half*128 + (t&127), n-chunk = t>>7 (256 n each).
//   Partials combined deterministically via SMEM.
// ===========================================================================
__global__ void __launch_bounds__(256)
ctx_softmax_k(const __half2* __restrict__ sh2,
              const float* __restrict__ sc_e, const float* __restrict__ sc_t,
              float* __restrict__ ce, float* __restrict__ ct)
{
    int b = blockIdx.x >> 1;
    int half = blockIdx.x & 1;
    int t = threadIdx.x;
    __shared__ float sae[512], sat[512], red[256];
    __shared__ float pex[2][128], pey[2][128], ptx[2][128], pty[2][128];

    // both softmaxes (proven 256-thread reduction pattern)
    float e0v = sc_e[b * 512 + t], e1v = sc_e[b * 512 + t + 256];
    float t0v = sc_t[b * 512 + t], t1v = sc_t[b * 512 + t + 256];
    red[t] = fmaxf(e0v, e1v);
    __syncthreads();
    for (int s = 128; s > 0; s >>= 1) {
        if (t < s) red[t] = fmaxf(red[t], red[t + s]);
        __syncthreads();
    }
    float mxe = red[0];
    __syncthreads();
    red[t] = fmaxf(t0v, t1v);
    __syncthreads();
    for (int s = 128; s > 0; s >>= 1) {
        if (t < s) red[t] = fmaxf(red[t], red[t + s]);
        __syncthreads();
    }
    float mxt = red[0];
    __syncthreads();
    float ee0 = expf(e0v - mxe), ee1 = expf(e1v - mxe);
    float tt0 = expf(t0v - mxt), tt1 = expf(t1v - mxt);
    red[t] = ee0 + ee1;
    __syncthreads();
    for (int s = 128; s > 0; s >>= 1) {
        if (t < s) red[t] += red[t + s];
        __syncthreads();
    }
    float inve = 1.f / red[0];
    __syncthreads();
    red[t] = tt0 + tt1;
    __syncthreads();
    for (int s = 128; s > 0; s >>= 1) {
        if (t < s) red[t] += red[t + s];
        __syncthreads();
    }
    float invt = 1.f / red[0];
    __syncthreads();
    sae[t] = ee0 * inve; sae[t + 256] = ee1 * inve;
    sat[t] = tt0 * invt; sat[t + 256] = tt1 * invt;
    __syncthreads();

    // context: 2 n-chunks in parallel
    int hh = t & 127;
    int nc = t >> 7;
    int h2 = half * 128 + hh;
    const __half2* Sb = sh2 + (size_t)b * 131072 + h2;
    float sex = 0.f, sey = 0.f, stx = 0.f, sty = 0.f;
    int n0 = nc * 256;
#pragma unroll 16
    for (int n = n0; n < n0 + 256; n++) {
        float2 f = __half22float2(Sb[(size_t)n * 256]);
        float a = sae[n], w = sat[n];
        sex += a * f.x;  sey += a * f.y;
        stx += w * f.x;  sty += w * f.y;
    }
    pex[nc][hh] = sex; pey[nc][hh] = sey;
    ptx[nc][hh] = stx; pty[nc][hh] = sty;
    __syncthreads();
    if (t < 128) {
        int h = half * 256 + t * 2;
        ce[b * 512 + h]     = pex[0][t] + pex[1][t];
        ce[b * 512 + h + 1] = pey[0][t] + pey[1][t];
        ct[b * 512 + h]     = ptx[0][t] + ptx[1][t];
        ct[b * 512 + h + 1] = pty[0][t] + pty[1][t];
    }
}

// ===========================================================================
extern "C" void kernel_launch(void* const* d_in, const int* in_sizes, int n_in,
                              void* d_out, int out_size)
{
    const float* stat = (const float*)d_in[0];   // (128,512,512)
    const float* semb = (const float*)d_in[1];   // (128,1,512)
    const float* dech = (const float*)d_in[2];   // (128,1,512)
    const float* tgth = (const float*)d_in[3];   // (128,1,512)
    const float* lhh  = (const float*)d_in[4];   // (1,128,512)
    const float* ptrv = (const float*)d_in[5];   // (1,1,512)
    const float* ptrW = (const float*)d_in[6];   // (1,512,1536)
    const float* encv = (const float*)d_in[7];   // (1,1,512)
    const float* encW = (const float*)d_in[8];   // (1,512,1024)
    const float* tgtv = (const float*)d_in[9];   // (1,1,512)
    const float* tgtW = (const float*)d_in[10];  // (1,512,1024)
    const float* wih  = (const float*)d_in[11];  // (1536,512)
    const float* whh  = (const float*)d_in[12];  // (1536,512)
    const float* bih  = (const float*)d_in[13];
    const float* bhh  = (const float*)d_in[14];
    float* out = (float*)d_out;

    unsigned char* base = nullptr;
    cudaGetSymbolAddress((void**)&base, g_scratch);
    __half* sh = (__half*)(base + OFF_SH);
    __half* bhp = (__half*)(base + OFF_BH);
    float* FL = (float*)(base + OFF_FL);
    float* gx     = FL + FO_GX;
    float* gh     = FL + FO_GH;
    float* hnew   = FL + FO_HNEW;
    float* denc   = FL + FO_DENC;
    float* dtgt   = FL + FO_DTGT;
    float* sstate = FL + FO_SSTATE;
    float* cptr   = FL + FO_CPTR;
    float* ctptr  = FL + FO_CTPTR;
    float* ctxe   = FL + FO_CTXE;
    float* ctxt   = FL + FO_CTXT;
    float* sc_e   = FL + FO_SCE;
    float* sc_t   = FL + FO_SCT;

    // Attribute cache: set once on the (uncaptured) correctness call.
    static bool attr_done = false;
    if (!attr_done) {
        cudaFuncSetAttribute(big_mma_et_k, cudaFuncAttributeMaxDynamicSharedMemorySize,
                             SMEM_ET);
        cudaFuncSetAttribute(big_mma_ptr_k, cudaFuncAttributeMaxDynamicSharedMemorySize,
                             SMEM_PTR);
        attr_done = true;
    }

    // conversions (merged into one launch; both paths register-light)
    convert_all_k<<<33536, 256>>>(encW, tgtW, ptrW, stat, (__half2*)bhp, (__half2*)sh);

    // GRU input/hidden GEMMs (z-batched)
    small_gemm3_k<<<dim3(24, 4, 2), 256>>>(
        dech, wih, 512, 0, gx, 1536,
        lhh,  whh, 512, 0, gh, 1536,
        lhh,  whh, 512, 0, gh, 1536);
    gru_gates_k<<<256, 256>>>(gx, gh, bih, bhh, lhh, hnew, out + 65536);

    // per-batch bias projections (z-batched)
    small_gemm3_k<<<dim3(8, 4, 3), 256>>>(
        hnew, encW, 1024, 512,  denc,   512,
        tgth, tgtW, 1024, 512,  dtgt,   512,
        semb, ptrW, 1536, 1024, sstate, 512);

    // enc/tgt GEMM -> scores
    big_mma_et_k<<<dim3(2, 512), 256, SMEM_ET>>>(sh, bhp, denc, dtgt,
                                                 encv, tgtv, sc_e, sc_t);

    // fused softmax + contexts (2x n-parallel)
    ctx_softmax_k<<<256, 256>>>((const __half2*)sh, sc_e, sc_t, ctxe, ctxt);

    // context projections
    small_gemm3_k<<<dim3(8, 4, 2), 256>>>(
        ctxe, ptrW, 1536, 512, cptr,  512,
        ctxt, ptrW, 1536, 512, ctptr, 512,
        ctxt, ptrW, 1536, 512, ctptr, 512);

    // ptr GEMM with fused final pointer-score epilogue -> probs
    big_mma_ptr_k<<<512, 256, SMEM_PTR>>>(sh, bhp, cptr, ctptr, sstate, ptrv, out);
}